// round 13
// baseline (speedup 1.0000x reference)
#include <cuda_runtime.h>
#include <cuda_fp16.h>
#include <cstdint>

// Problem constants
#define NRES 768
#define TF   21
#define MSADIM 49
#define CZ   128
#define CM   256
#define MSA_OUT_ELEMS (512u*768u*256u)   // 100663296
#define TOT_ITEMS 15360                  // 5 * 3072
#define GRID_U 444                       // 3 CTAs per SM

// ---------------- device scratch ----------------
__device__ float  g_tfi[NRES * CZ];
__device__ float  g_tfj[NRES * CZ];
__device__ float  g_comb[NRES * CM];
__device__ __half g_wh[48 * CM];         // fp16 weights k=0..47
__device__ float  g_w48[CM];             // fp32 weight row k=48
__device__ float  g_w2[396 * CZ];        // W2[pos*6+chain] = w_rel[pos] + w_rel[67+chain]

// ---------------- smem layout per CTA (bytes) ----------------
// W    [48][264h] stride 528   @ 0       (25344)
// raw0 32x49 f32               @ 25344   (6272)
// raw1                         @ 31616   (6272)
// w48  fp32[256]               @ 37888   (1024)
// A_hi [32][56h]  stride 112   @ 38912   (3584)
// stg  32 rows x 1056B         @ 42496   (33792) -> 76288  (3 CTAs: 228.9KB)
#define W_STRIDE 528
#define A_STRIDE 112
#define OFF_W    0
#define OFF_RAW0 25344
#define OFF_RAW1 31616
#define OFF_W48  37888
#define OFF_AHI  38912
#define OFF_STG  42496
#define STG_STRIDE 1056
#define U_SMEM   76288

// ---------------- helpers ----------------
__device__ __forceinline__ uint32_t smem_u32(const void* p) {
    uint32_t a;
    asm("{ .reg .u64 t; cvta.to.shared.u64 t, %1; cvt.u32.u64 %0, t; }" : "=r"(a) : "l"(p));
    return a;
}
__device__ __forceinline__ void cp16(uint32_t dst, const void* src) {
    asm volatile("cp.async.cg.shared.global [%0], [%1], 16;" :: "r"(dst), "l"(src) : "memory");
}
__device__ __forceinline__ void cp_commit() {
    asm volatile("cp.async.commit_group;" ::: "memory");
}
__device__ __forceinline__ void cp_wait_all() {
    asm volatile("cp.async.wait_group 0;" ::: "memory");
}

#define LDSM_X4(r, addr) \
    asm volatile("ldmatrix.sync.aligned.m8n8.x4.shared.b16 {%0,%1,%2,%3}, [%4];" \
                 : "=r"((r)[0]), "=r"((r)[1]), "=r"((r)[2]), "=r"((r)[3]) : "r"(addr))
#define LDSM_X4T(r, addr) \
    asm volatile("ldmatrix.sync.aligned.m8n8.x4.trans.shared.b16 {%0,%1,%2,%3}, [%4];" \
                 : "=r"((r)[0]), "=r"((r)[1]), "=r"((r)[2]), "=r"((r)[3]) : "r"(addr))
#define MMAF16(d, a, b0v, b1v) \
    asm volatile("mma.sync.aligned.m16n8k16.row.col.f32.f16.f16.f32 " \
                 "{%0,%1,%2,%3}, {%4,%5,%6,%7}, {%8,%9}, {%0,%1,%2,%3};" \
                 : "+f"((d)[0]), "+f"((d)[1]), "+f"((d)[2]), "+f"((d)[3]) \
                 : "r"((a)[0]), "r"((a)[1]), "r"((a)[2]), "r"((a)[3]), \
                   "r"(b0v), "r"(b1v))

// ---------------- kernel 1: precompute ----------------
// blocks 0..95: per-residue embeddings; 96..144: wconv; 145..540: W2 table.
__global__ void __launch_bounds__(256) pre_kernel(
        const float* __restrict__ tf,
        const float* __restrict__ wzi, const float* __restrict__ bzi,
        const float* __restrict__ wzj, const float* __restrict__ bzj,
        const float* __restrict__ wm,  const float* __restrict__ bm,
        const float* __restrict__ bmsa, const float* __restrict__ wmsa,
        const float* __restrict__ wrel) {
    int c = threadIdx.x;
    if (blockIdx.x >= 145) {
        int widx = blockIdx.x - 145;            // 0..395
        if (c < CZ) {
            int pos = widx / 6;
            int chain = widx - 6 * pos;
            g_w2[widx * CZ + c] = wrel[pos * CZ + c] + wrel[(67 + chain) * CZ + c];
        }
        return;
    }
    if (blockIdx.x >= 96) {
        int k = blockIdx.x - 96;   // 0..48
        float v = wmsa[k * CM + c];
        if (k < 48) g_wh[k * CM + c] = __float2half_rn(v);
        else        g_w48[c] = v;
        return;
    }
    __shared__ float swm[TF * CM];
    __shared__ float swi[TF * CZ];
    __shared__ float swj[TF * CZ];
    __shared__ float st[8 * TF];

    for (int g = c; g < TF * CM; g += 256) swm[g] = wm[g];
    for (int g = c; g < TF * CZ; g += 256) { swi[g] = wzi[g]; swj[g] = wzj[g]; }
    int i0 = blockIdx.x * 8;
    for (int g = c; g < 8 * TF; g += 256) st[g] = tf[i0 * TF + g];
    __syncthreads();

    float bmv = bm[c] + bmsa[c];
    float bzi_v = (c < CZ) ? bzi[c] : 0.0f;
    float bzj_v = (c < CZ) ? bzj[c] : 0.0f;

#pragma unroll 1
    for (int r = 0; r < 8; r++) {
        const float* t = st + r * TF;
        float am = bmv;
#pragma unroll
        for (int k = 0; k < TF; k++) am += t[k] * swm[k * CM + c];
        g_comb[(i0 + r) * CM + c] = am;

        if (c < CZ) {
            float ai = bzi_v;
            float aj = bzj_v;
#pragma unroll
            for (int k = 0; k < TF; k++) {
                float tv = t[k];
                ai += tv * swi[k * CZ + c];
                aj += tv * swj[k * CZ + c];
            }
            g_tfi[(i0 + r) * CZ + c] = ai;
            g_tfj[(i0 + r) * CZ + c] = aj;
        }
    }
}

// ---------------- kernel 2: unified persistent msa + pair ----------------
__global__ void __launch_bounds__(256, 3) uni_kernel(const float* __restrict__ msa,
                                                     const int* __restrict__ res,
                                                     const int* __restrict__ sym,
                                                     const int* __restrict__ asym,
                                                     const int* __restrict__ ent,
                                                     const float* __restrict__ w_rel,
                                                     const float* __restrict__ b_rel,
                                                     float* __restrict__ out) {
    extern __shared__ char smem[];
    uint32_t sb = smem_u32(smem);
    int tid = threadIdx.x;
    int lane = tid & 31;
    int wid = tid >> 5;
    int bid = blockIdx.x;
    float* msa_out  = out;
    float* pair_out = out + MSA_OUT_ELEMS;

    // stage weights + w48 once
    for (int g = tid; g < 1536; g += 256) {
        int row = g >> 5;
        int c = g & 31;
        cp16(sb + OFF_W + row * W_STRIDE + c * 16, (const char*)g_wh + row * 512 + c * 16);
    }
    if (tid < 64) cp16(sb + OFF_W48 + tid * 16, (const char*)g_w48 + tid * 16);
    // prefetch first msa tile raw
    {
        int wf = bid;
        while (wf < TOT_ITEMS && (wf % 5) == 4) wf += GRID_U;
        if (wf < TOT_ITEMS) {
            int m = (wf / 5) * 4 + (wf % 5);
            const char* src = (const char*)msa + (long)m * 6272;
            for (int g = tid; g < 392; g += 256)
                cp16(sb + OFF_RAW0 + g * 16, src + g * 16);
        }
    }
    cp_commit();

    // per-thread ldmatrix addresses
    uint32_t aoff = (uint32_t)((lane & 15) * A_STRIDE + (lane >> 4) * 16);
    uint32_t ahi_base = sb + OFF_AHI + aoff;
    uint32_t boff = (uint32_t)(((lane & 7) + ((lane >> 3) & 1) * 8) * W_STRIDE +
                               (wid * 32 + (lane >> 4) * 8) * 2);
    uint32_t b_base = sb + OFF_W + boff;
    int qr = lane >> 2;
    int qc = (lane & 3) * 2;
    int msa_cnt = 0;

    const float* s_w48f = (const float*)(smem + OFF_W48);

    // ---- load B fragments ONCE (weights are tile-invariant) ----
    cp_wait_all();
    __syncthreads();
    uint32_t bfr[3][8];
#pragma unroll
    for (int ks = 0; ks < 3; ks++) {
        LDSM_X4T(&bfr[ks][0], b_base + ks * 16 * W_STRIDE);
        LDSM_X4T(&bfr[ks][4], b_base + ks * 16 * W_STRIDE + 32);  // +16 ch
    }

    for (int w = bid; w < TOT_ITEMS; w += GRID_U) {
        if ((w % 5) != 4) {
            // ================= msa tile (32 rows x 256 ch) =================
            int t = (w / 5) * 4 + (w % 5);
            uint32_t raw_cur = (msa_cnt & 1) ? OFF_RAW1 : OFF_RAW0;
            uint32_t raw_nxt = (msa_cnt & 1) ? OFF_RAW0 : OFF_RAW1;
            msa_cnt++;
            const float* rawf = (const float*)(smem + raw_cur);

            cp_wait_all();
            __syncthreads();   // raw ready; prev tile done

            // convert raw -> A fp16 (k<48)
            for (int g = tid; g < 768; g += 256) {
                int row = g / 24;
                int p = g - row * 24;
                float a0 = rawf[row * 49 + 2 * p];
                float a1 = rawf[row * 49 + 2 * p + 1];
                __half h0 = __float2half_rn(a0);
                __half h1 = __float2half_rn(a1);
                uint32_t o = row * A_STRIDE + p * 4;
                *(__half2*)(smem + OFF_AHI + o) = __halves2half2(h0, h1);
            }
            __syncthreads();   // A ready

            // prefetch next msa tile's raw (overlaps MMA)
            {
                int wn = w + GRID_U;
                while (wn < TOT_ITEMS && (wn % 5) == 4) wn += GRID_U;
                if (wn < TOT_ITEMS) {
                    int m2 = (wn / 5) * 4 + (wn % 5);
                    const char* src = (const char*)msa + (long)m2 * 6272;
                    for (int g = tid; g < 392; g += 256)
                        cp16(sb + raw_nxt + g * 16, src + g * 16);
                }
            }
            cp_commit();

            // MMA: 3 k-steps, single term; B resident
            float d[2][4][4];
#pragma unroll
            for (int mt = 0; mt < 2; mt++)
#pragma unroll
                for (int nt = 0; nt < 4; nt++)
#pragma unroll
                    for (int i = 0; i < 4; i++) d[mt][nt][i] = 0.0f;

#pragma unroll
            for (int ks = 0; ks < 3; ks++) {
                uint32_t ak = ks * 32;
                uint32_t af[2][4];
                LDSM_X4(af[0], ahi_base + ak);
                LDSM_X4(af[1], ahi_base + 16 * A_STRIDE + ak);
#pragma unroll
                for (int mt = 0; mt < 2; mt++)
#pragma unroll
                    for (int nt = 0; nt < 4; nt++)
                        MMAF16(d[mt][nt], af[mt], bfr[ks][nt * 2], bfr[ks][nt * 2 + 1]);
            }

            // ---- epilogue: single-pass 32-row staging, 2 syncs ----
            long rowbase = (long)t * 32;
            int n0 = (int)(rowbase % NRES);
            {
                char* stg = smem + OFF_STG;
                int chb = (wid * 32 + qc) * 4;
#pragma unroll
                for (int p = 0; p < 2; p++)
#pragma unroll
                    for (int nt = 0; nt < 4; nt++) {
                        *(float2*)(stg + (p * 16 + qr) * STG_STRIDE + chb + nt * 32) =
                            make_float2(d[p][nt][0], d[p][nt][1]);
                        *(float2*)(stg + (p * 16 + qr + 8) * STG_STRIDE + chb + nt * 32) =
                            make_float2(d[p][nt][2], d[p][nt][3]);
                    }
            }
            __syncthreads();
#pragma unroll
            for (int q = 0; q < 8; q++) {
                int g = tid + q * 256;
                int row = g >> 6;        // 0..31
                int c4 = g & 63;
                float4 v = *(const float4*)(smem + OFF_STG + row * STG_STRIDE + c4 * 16);
                float4 w48v = *(const float4*)(s_w48f + c4 * 4);
                float a48v = rawf[row * 49 + 48];
                float4 cb = *(const float4*)(g_comb + (n0 + row) * CM + c4 * 4);
                float4 o = make_float4(v.x + a48v * w48v.x + cb.x,
                                       v.y + a48v * w48v.y + cb.y,
                                       v.z + a48v * w48v.z + cb.z,
                                       v.w + a48v * w48v.w + cb.w);
                *(float4*)(msa_out + (rowbase + row) * (long)CM + c4 * 4) = o;
            }
            __syncthreads();
        } else {
            // ================= pair tile =================
            int p = w / 5;
            int i = p >> 2;
            int jstart = (p & 3) * 192;
            int jl = tid >> 5;   // 8 j-lanes

            int res_i  = __ldg(res + i);
            int sym_i  = __ldg(sym + i);
            int asym_i = __ldg(asym + i);
            int ent_i  = __ldg(ent + i);

            float4 b4 = ((const float4*)b_rel)[lane];
            float4 ti = ((const float4*)(g_tfi + i * CZ))[lane];
            float4 base4 = make_float4(b4.x + ti.x, b4.y + ti.y, b4.z + ti.z, b4.w + ti.w);
            const float4* W4 = (const float4*)w_rel;
            const float4* W24 = (const float4*)g_w2;
            float4 w66 = W4[66 * 32 + lane];

#pragma unroll 4
            for (int it = 0; it < 24; it++) {
                int j = jstart + it * 8 + jl;
                int rj = __ldg(res + j), sj = __ldg(sym + j), aj = __ldg(asym + j);

                int off = res_i - rj + 32;
                off = min(max(off, 0), 64);
                int pos = (asym_i == aj) ? off : 65;

                int ed = ent_i - sj;
                float entf = (float)ed;

                int cc = sym_i - sj + 2;
                cc = min(max(cc, 0), 4);
                int chain = (ed != 0) ? cc : 5;

                // combined gather: w_rel[pos] + w_rel[67+chain]
                float4 wv = W24[(pos * 6 + chain) * 32 + lane];
                float4 tj = ((const float4*)(g_tfj + j * CZ))[lane];

                float4 o;
                o.x = base4.x + wv.x + entf * w66.x + tj.x;
                o.y = base4.y + wv.y + entf * w66.y + tj.y;
                o.z = base4.z + wv.z + entf * w66.z + tj.z;
                o.w = base4.w + wv.w + entf * w66.w + tj.w;

                ((float4*)(pair_out + ((size_t)i * NRES + j) * CZ))[lane] = o;
            }
        }
    }
}

// ---------------- launch ----------------
extern "C" void kernel_launch(void* const* d_in, const int* in_sizes, int n_in,
                              void* d_out, int out_size) {
    const float* tf     = (const float*)d_in[0];
    const float* msa    = (const float*)d_in[1];
    const int*   res    = (const int*)d_in[2];
    const int*   sym    = (const int*)d_in[3];
    const int*   asym   = (const int*)d_in[4];
    const int*   ent    = (const int*)d_in[5];
    const float* w_zi   = (const float*)d_in[6];
    const float* b_zi   = (const float*)d_in[7];
    const float* w_zj   = (const float*)d_in[8];
    const float* b_zj   = (const float*)d_in[9];
    const float* w_m    = (const float*)d_in[10];
    const float* b_m    = (const float*)d_in[11];
    const float* w_msa  = (const float*)d_in[12];
    const float* b_msa  = (const float*)d_in[13];
    const float* w_rel  = (const float*)d_in[14];
    const float* b_rel  = (const float*)d_in[15];

    cudaFuncSetAttribute(uni_kernel, cudaFuncAttributeMaxDynamicSharedMemorySize, U_SMEM);

    pre_kernel<<<96 + 49 + 396, 256>>>(tf, w_zi, b_zi, w_zj, b_zj, w_m, b_m, b_msa,
                                       w_msa, w_rel);
    uni_kernel<<<GRID_U, 256, U_SMEM>>>(msa, res, sym, asym, ent, w_rel, b_rel,
                                        (float*)d_out);
}

// round 14
// speedup vs baseline: 1.0233x; 1.0233x over previous
#include <cuda_runtime.h>
#include <cuda_fp16.h>
#include <cstdint>

// Problem constants
#define NRES 768
#define TF   21
#define MSADIM 49
#define CZ   128
#define CM   256
#define MSA_OUT_ELEMS (512u*768u*256u)   // 100663296
#define TOT_ITEMS 15360                  // 5 * 3072
#define GRID_U 444                       // 3 CTAs per SM

// ---------------- device scratch ----------------
__device__ float  g_tfi[NRES * CZ];
__device__ float  g_tfj[NRES * CZ];
__device__ float  g_comb[NRES * CM];
__device__ __half g_wh[48 * CM];         // fp16 weights k=0..47
__device__ float  g_w48[CM];             // fp32 weight row k=48
__device__ float  g_w2[396 * CZ];        // W2[pos*6+chain] = w_rel[pos] + w_rel[67+chain]

// ---------------- smem layout per CTA (bytes) ----------------
// W    [48][264h] stride 528   @ 0       (25344)  -- DEAD after bfr load;
//                                                    reused as stg rows 0..23
// raw0 32x49 f32               @ 25344   (6272)
// raw1                         @ 31616   (6272)
// w48  fp32[256]               @ 37888   (1024)
// A_hi [32][56h]  stride 112   @ 38912   (3584)
// stgB rows 24..31 x 1056B     @ 42496   (8448)  -> 50944 total (3 CTAs: 152.8KB)
#define W_STRIDE 528
#define A_STRIDE 112
#define OFF_W    0
#define OFF_RAW0 25344
#define OFF_RAW1 31616
#define OFF_W48  37888
#define OFF_AHI  38912
#define OFF_STGB 42496
#define STG_STRIDE 1056
#define U_SMEM   50944

// ---------------- helpers ----------------
__device__ __forceinline__ uint32_t smem_u32(const void* p) {
    uint32_t a;
    asm("{ .reg .u64 t; cvta.to.shared.u64 t, %1; cvt.u32.u64 %0, t; }" : "=r"(a) : "l"(p));
    return a;
}
__device__ __forceinline__ void cp16(uint32_t dst, const void* src) {
    asm volatile("cp.async.cg.shared.global [%0], [%1], 16;" :: "r"(dst), "l"(src) : "memory");
}
__device__ __forceinline__ void cp_commit() {
    asm volatile("cp.async.commit_group;" ::: "memory");
}
__device__ __forceinline__ void cp_wait_all() {
    asm volatile("cp.async.wait_group 0;" ::: "memory");
}

#define LDSM_X4(r, addr) \
    asm volatile("ldmatrix.sync.aligned.m8n8.x4.shared.b16 {%0,%1,%2,%3}, [%4];" \
                 : "=r"((r)[0]), "=r"((r)[1]), "=r"((r)[2]), "=r"((r)[3]) : "r"(addr))
#define LDSM_X4T(r, addr) \
    asm volatile("ldmatrix.sync.aligned.m8n8.x4.trans.shared.b16 {%0,%1,%2,%3}, [%4];" \
                 : "=r"((r)[0]), "=r"((r)[1]), "=r"((r)[2]), "=r"((r)[3]) : "r"(addr))
#define MMAF16(d, a, b0v, b1v) \
    asm volatile("mma.sync.aligned.m16n8k16.row.col.f32.f16.f16.f32 " \
                 "{%0,%1,%2,%3}, {%4,%5,%6,%7}, {%8,%9}, {%0,%1,%2,%3};" \
                 : "+f"((d)[0]), "+f"((d)[1]), "+f"((d)[2]), "+f"((d)[3]) \
                 : "r"((a)[0]), "r"((a)[1]), "r"((a)[2]), "r"((a)[3]), \
                   "r"(b0v), "r"(b1v))

// ---------------- kernel 1: precompute ----------------
// blocks 0..95: per-residue embeddings; 96..144: wconv; 145..540: W2 table.
__global__ void __launch_bounds__(256) pre_kernel(
        const float* __restrict__ tf,
        const float* __restrict__ wzi, const float* __restrict__ bzi,
        const float* __restrict__ wzj, const float* __restrict__ bzj,
        const float* __restrict__ wm,  const float* __restrict__ bm,
        const float* __restrict__ bmsa, const float* __restrict__ wmsa,
        const float* __restrict__ wrel) {
    int c = threadIdx.x;
    if (blockIdx.x >= 145) {
        int widx = blockIdx.x - 145;            // 0..395
        if (c < CZ) {
            int pos = widx / 6;
            int chain = widx - 6 * pos;
            g_w2[widx * CZ + c] = wrel[pos * CZ + c] + wrel[(67 + chain) * CZ + c];
        }
        return;
    }
    if (blockIdx.x >= 96) {
        int k = blockIdx.x - 96;   // 0..48
        float v = wmsa[k * CM + c];
        if (k < 48) g_wh[k * CM + c] = __float2half_rn(v);
        else        g_w48[c] = v;
        return;
    }
    __shared__ float swm[TF * CM];
    __shared__ float swi[TF * CZ];
    __shared__ float swj[TF * CZ];
    __shared__ float st[8 * TF];

    for (int g = c; g < TF * CM; g += 256) swm[g] = wm[g];
    for (int g = c; g < TF * CZ; g += 256) { swi[g] = wzi[g]; swj[g] = wzj[g]; }
    int i0 = blockIdx.x * 8;
    for (int g = c; g < 8 * TF; g += 256) st[g] = tf[i0 * TF + g];
    __syncthreads();

    float bmv = bm[c] + bmsa[c];
    float bzi_v = (c < CZ) ? bzi[c] : 0.0f;
    float bzj_v = (c < CZ) ? bzj[c] : 0.0f;

#pragma unroll 1
    for (int r = 0; r < 8; r++) {
        const float* t = st + r * TF;
        float am = bmv;
#pragma unroll
        for (int k = 0; k < TF; k++) am += t[k] * swm[k * CM + c];
        g_comb[(i0 + r) * CM + c] = am;

        if (c < CZ) {
            float ai = bzi_v;
            float aj = bzj_v;
#pragma unroll
            for (int k = 0; k < TF; k++) {
                float tv = t[k];
                ai += tv * swi[k * CZ + c];
                aj += tv * swj[k * CZ + c];
            }
            g_tfi[(i0 + r) * CZ + c] = ai;
            g_tfj[(i0 + r) * CZ + c] = aj;
        }
    }
}

// ---------------- kernel 2: unified persistent msa + pair ----------------
__global__ void __launch_bounds__(256, 3) uni_kernel(const float* __restrict__ msa,
                                                     const int* __restrict__ res,
                                                     const int* __restrict__ sym,
                                                     const int* __restrict__ asym,
                                                     const int* __restrict__ ent,
                                                     const float* __restrict__ w_rel,
                                                     const float* __restrict__ b_rel,
                                                     float* __restrict__ out) {
    extern __shared__ char smem[];
    uint32_t sb = smem_u32(smem);
    int tid = threadIdx.x;
    int lane = tid & 31;
    int wid = tid >> 5;
    int bid = blockIdx.x;
    float* msa_out  = out;
    float* pair_out = out + MSA_OUT_ELEMS;

    // stage weights + w48 once
    for (int g = tid; g < 1536; g += 256) {
        int row = g >> 5;
        int c = g & 31;
        cp16(sb + OFF_W + row * W_STRIDE + c * 16, (const char*)g_wh + row * 512 + c * 16);
    }
    if (tid < 64) cp16(sb + OFF_W48 + tid * 16, (const char*)g_w48 + tid * 16);
    // prefetch first msa tile raw
    {
        int wf = bid;
        while (wf < TOT_ITEMS && (wf % 5) == 4) wf += GRID_U;
        if (wf < TOT_ITEMS) {
            int m = (wf / 5) * 4 + (wf % 5);
            const char* src = (const char*)msa + (long)m * 6272;
            for (int g = tid; g < 392; g += 256)
                cp16(sb + OFF_RAW0 + g * 16, src + g * 16);
        }
    }
    cp_commit();

    // per-thread ldmatrix addresses
    uint32_t aoff = (uint32_t)((lane & 15) * A_STRIDE + (lane >> 4) * 16);
    uint32_t ahi_base = sb + OFF_AHI + aoff;
    uint32_t boff = (uint32_t)(((lane & 7) + ((lane >> 3) & 1) * 8) * W_STRIDE +
                               (wid * 32 + (lane >> 4) * 8) * 2);
    uint32_t b_base = sb + OFF_W + boff;
    int qr = lane >> 2;
    int qc = (lane & 3) * 2;
    int msa_cnt = 0;

    const float* s_w48f = (const float*)(smem + OFF_W48);

    // ---- load B fragments ONCE; W smem region becomes dead after this ----
    cp_wait_all();
    __syncthreads();
    uint32_t bfr[3][8];
#pragma unroll
    for (int ks = 0; ks < 3; ks++) {
        LDSM_X4T(&bfr[ks][0], b_base + ks * 16 * W_STRIDE);
        LDSM_X4T(&bfr[ks][4], b_base + ks * 16 * W_STRIDE + 32);  // +16 ch
    }

    for (int w = bid; w < TOT_ITEMS; w += GRID_U) {
        if ((w % 5) != 4) {
            // ================= msa tile (32 rows x 256 ch) =================
            int t = (w / 5) * 4 + (w % 5);
            uint32_t raw_cur = (msa_cnt & 1) ? OFF_RAW1 : OFF_RAW0;
            uint32_t raw_nxt = (msa_cnt & 1) ? OFF_RAW0 : OFF_RAW1;
            msa_cnt++;
            const float* rawf = (const float*)(smem + raw_cur);

            cp_wait_all();
            __syncthreads();   // raw ready; prev tile done

            // convert raw -> A fp16 (k<48)
            for (int g = tid; g < 768; g += 256) {
                int row = g / 24;
                int p = g - row * 24;
                float a0 = rawf[row * 49 + 2 * p];
                float a1 = rawf[row * 49 + 2 * p + 1];
                __half h0 = __float2half_rn(a0);
                __half h1 = __float2half_rn(a1);
                uint32_t o = row * A_STRIDE + p * 4;
                *(__half2*)(smem + OFF_AHI + o) = __halves2half2(h0, h1);
            }
            __syncthreads();   // A ready

            // prefetch next msa tile's raw (overlaps MMA)
            {
                int wn = w + GRID_U;
                while (wn < TOT_ITEMS && (wn % 5) == 4) wn += GRID_U;
                if (wn < TOT_ITEMS) {
                    int m2 = (wn / 5) * 4 + (wn % 5);
                    const char* src = (const char*)msa + (long)m2 * 6272;
                    for (int g = tid; g < 392; g += 256)
                        cp16(sb + raw_nxt + g * 16, src + g * 16);
                }
            }
            cp_commit();

            // MMA: 3 k-steps, single term; B resident
            float d[2][4][4];
#pragma unroll
            for (int mt = 0; mt < 2; mt++)
#pragma unroll
                for (int nt = 0; nt < 4; nt++)
#pragma unroll
                    for (int i = 0; i < 4; i++) d[mt][nt][i] = 0.0f;

#pragma unroll
            for (int ks = 0; ks < 3; ks++) {
                uint32_t ak = ks * 32;
                uint32_t af[2][4];
                LDSM_X4(af[0], ahi_base + ak);
                LDSM_X4(af[1], ahi_base + 16 * A_STRIDE + ak);
#pragma unroll
                for (int mt = 0; mt < 2; mt++)
#pragma unroll
                    for (int nt = 0; nt < 4; nt++)
                        MMAF16(d[mt][nt], af[mt], bfr[ks][nt * 2], bfr[ks][nt * 2 + 1]);
            }

            // ---- epilogue: single-pass 32-row staging (rows 0..23 reuse the
            //      dead W region; rows 24..31 in stgB), 2 syncs ----
            long rowbase = (long)t * 32;
            int n0 = (int)(rowbase % NRES);
            {
                char* stgA = smem;               // rows 0..23
                char* stgB = smem + OFF_STGB;    // rows 24..31
                int chb = (wid * 32 + qc) * 4;
#pragma unroll
                for (int nt = 0; nt < 4; nt++) {
                    // p=0: rows qr (0..7) and qr+8 (8..15) -> A
                    *(float2*)(stgA + qr * STG_STRIDE + chb + nt * 32) =
                        make_float2(d[0][nt][0], d[0][nt][1]);
                    *(float2*)(stgA + (qr + 8) * STG_STRIDE + chb + nt * 32) =
                        make_float2(d[0][nt][2], d[0][nt][3]);
                    // p=1: rows 16+qr (16..23) -> A ; rows 24+qr -> B
                    *(float2*)(stgA + (16 + qr) * STG_STRIDE + chb + nt * 32) =
                        make_float2(d[1][nt][0], d[1][nt][1]);
                    *(float2*)(stgB + qr * STG_STRIDE + chb + nt * 32) =
                        make_float2(d[1][nt][2], d[1][nt][3]);
                }
            }
            __syncthreads();
#pragma unroll
            for (int q = 0; q < 8; q++) {
                int g = tid + q * 256;
                int row = g >> 6;        // 0..31; q<6 -> row<24 (region A)
                int c4 = g & 63;
                float4 v = (q < 6)
                    ? *(const float4*)(smem + row * STG_STRIDE + c4 * 16)
                    : *(const float4*)(smem + OFF_STGB + (row - 24) * STG_STRIDE + c4 * 16);
                float4 w48v = *(const float4*)(s_w48f + c4 * 4);
                float a48v = rawf[row * 49 + 48];
                float4 cb = *(const float4*)(g_comb + (n0 + row) * CM + c4 * 4);
                float4 o = make_float4(v.x + a48v * w48v.x + cb.x,
                                       v.y + a48v * w48v.y + cb.y,
                                       v.z + a48v * w48v.z + cb.z,
                                       v.w + a48v * w48v.w + cb.w);
                *(float4*)(msa_out + (rowbase + row) * (long)CM + c4 * 4) = o;
            }
            __syncthreads();
        } else {
            // ================= pair tile =================
            int p = w / 5;
            int i = p >> 2;
            int jstart = (p & 3) * 192;
            int jl = tid >> 5;   // 8 j-lanes

            int res_i  = __ldg(res + i);
            int sym_i  = __ldg(sym + i);
            int asym_i = __ldg(asym + i);
            int ent_i  = __ldg(ent + i);

            float4 b4 = ((const float4*)b_rel)[lane];
            float4 ti = ((const float4*)(g_tfi + i * CZ))[lane];
            float4 base4 = make_float4(b4.x + ti.x, b4.y + ti.y, b4.z + ti.z, b4.w + ti.w);
            const float4* W4 = (const float4*)w_rel;
            const float4* W24 = (const float4*)g_w2;
            float4 w66 = W4[66 * 32 + lane];

#pragma unroll 4
            for (int it = 0; it < 24; it++) {
                int j = jstart + it * 8 + jl;
                int rj = __ldg(res + j), sj = __ldg(sym + j), aj = __ldg(asym + j);

                int off = res_i - rj + 32;
                off = min(max(off, 0), 64);
                int pos = (asym_i == aj) ? off : 65;

                int ed = ent_i - sj;
                float entf = (float)ed;

                int cc = sym_i - sj + 2;
                cc = min(max(cc, 0), 4);
                int chain = (ed != 0) ? cc : 5;

                // combined gather: w_rel[pos] + w_rel[67+chain]
                float4 wv = W24[(pos * 6 + chain) * 32 + lane];
                float4 tj = ((const float4*)(g_tfj + j * CZ))[lane];

                float4 o;
                o.x = base4.x + wv.x + entf * w66.x + tj.x;
                o.y = base4.y + wv.y + entf * w66.y + tj.y;
                o.z = base4.z + wv.z + entf * w66.z + tj.z;
                o.w = base4.w + wv.w + entf * w66.w + tj.w;

                ((float4*)(pair_out + ((size_t)i * NRES + j) * CZ))[lane] = o;
            }
        }
    }
}

// ---------------- launch ----------------
extern "C" void kernel_launch(void* const* d_in, const int* in_sizes, int n_in,
                              void* d_out, int out_size) {
    const float* tf     = (const float*)d_in[0];
    const float* msa    = (const float*)d_in[1];
    const int*   res    = (const int*)d_in[2];
    const int*   sym    = (const int*)d_in[3];
    const int*   asym   = (const int*)d_in[4];
    const int*   ent    = (const int*)d_in[5];
    const float* w_zi   = (const float*)d_in[6];
    const float* b_zi   = (const float*)d_in[7];
    const float* w_zj   = (const float*)d_in[8];
    const float* b_zj   = (const float*)d_in[9];
    const float* w_m    = (const float*)d_in[10];
    const float* b_m    = (const float*)d_in[11];
    const float* w_msa  = (const float*)d_in[12];
    const float* b_msa  = (const float*)d_in[13];
    const float* w_rel  = (const float*)d_in[14];
    const float* b_rel  = (const float*)d_in[15];

    cudaFuncSetAttribute(uni_kernel, cudaFuncAttributeMaxDynamicSharedMemorySize, U_SMEM);

    pre_kernel<<<96 + 49 + 396, 256>>>(tf, w_zi, b_zi, w_zj, b_zj, w_m, b_m, b_msa,
                                       w_msa, w_rel);
    uni_kernel<<<GRID_U, 256, U_SMEM>>>(msa, res, sym, asym, ent, w_rel, b_rel,
                                        (float*)d_out);
}

// round 15
// speedup vs baseline: 1.0469x; 1.0231x over previous
#include <cuda_runtime.h>
#include <cuda_fp16.h>
#include <cstdint>

// Problem constants
#define NRES 768
#define TF   21
#define MSADIM 49
#define CZ   128
#define CM   256
#define MSA_OUT_ELEMS (512u*768u*256u)   // 100663296
#define TOT_ITEMS 15360                  // 5 * 3072
#define GRID_U 444                       // 3 CTAs per SM

// ---------------- device scratch ----------------
__device__ float  g_tfi[NRES * CZ];
__device__ float  g_tfj[NRES * CZ];
__device__ float  g_comb[NRES * CM];
__device__ __half g_wh[48 * CM];         // fp16 weights k=0..47
__device__ float  g_w48[CM];             // fp32 weight row k=48
__device__ float  g_w3[2772 * CZ];       // W3[(pos*6+chain)*7+(ed+3)]
__device__ unsigned short g_idx[NRES * NRES];  // per-pair W3 row index

// ---------------- smem layout per CTA (bytes) ---- (R12 layout) ----
#define W_STRIDE 528
#define A_STRIDE 112
#define OFF_W    0
#define OFF_RAW0 25344
#define OFF_RAW1 31616
#define OFF_W48  37888
#define OFF_AHI  38912
#define OFF_STG  42496
#define STG_STRIDE 1056
#define U_SMEM   59392

// ---------------- helpers ----------------
__device__ __forceinline__ uint32_t smem_u32(const void* p) {
    uint32_t a;
    asm("{ .reg .u64 t; cvta.to.shared.u64 t, %1; cvt.u32.u64 %0, t; }" : "=r"(a) : "l"(p));
    return a;
}
__device__ __forceinline__ void cp16(uint32_t dst, const void* src) {
    asm volatile("cp.async.cg.shared.global [%0], [%1], 16;" :: "r"(dst), "l"(src) : "memory");
}
__device__ __forceinline__ void cp_commit() {
    asm volatile("cp.async.commit_group;" ::: "memory");
}
__device__ __forceinline__ void cp_wait_all() {
    asm volatile("cp.async.wait_group 0;" ::: "memory");
}

#define LDSM_X4(r, addr) \
    asm volatile("ldmatrix.sync.aligned.m8n8.x4.shared.b16 {%0,%1,%2,%3}, [%4];" \
                 : "=r"((r)[0]), "=r"((r)[1]), "=r"((r)[2]), "=r"((r)[3]) : "r"(addr))
#define LDSM_X4T(r, addr) \
    asm volatile("ldmatrix.sync.aligned.m8n8.x4.trans.shared.b16 {%0,%1,%2,%3}, [%4];" \
                 : "=r"((r)[0]), "=r"((r)[1]), "=r"((r)[2]), "=r"((r)[3]) : "r"(addr))
#define MMAF16(d, a, b0v, b1v) \
    asm volatile("mma.sync.aligned.m16n8k16.row.col.f32.f16.f16.f32 " \
                 "{%0,%1,%2,%3}, {%4,%5,%6,%7}, {%8,%9}, {%0,%1,%2,%3};" \
                 : "+f"((d)[0]), "+f"((d)[1]), "+f"((d)[2]), "+f"((d)[3]) \
                 : "r"((a)[0]), "r"((a)[1]), "r"((a)[2]), "r"((a)[3]), \
                   "r"(b0v), "r"(b1v))

// ---------------- kernel 1: precompute ----------------
// blocks 0..95: residue embeddings; 96..144: wconv;
// 145..1530: W3 table (1386 blocks x 2 rows); 1531..2298: idx table (768 blocks).
__global__ void __launch_bounds__(256) pre_kernel(
        const float* __restrict__ tf,
        const float* __restrict__ wzi, const float* __restrict__ bzi,
        const float* __restrict__ wzj, const float* __restrict__ bzj,
        const float* __restrict__ wm,  const float* __restrict__ bm,
        const float* __restrict__ bmsa, const float* __restrict__ wmsa,
        const float* __restrict__ wrel,
        const int* __restrict__ res, const int* __restrict__ sym,
        const int* __restrict__ asym, const int* __restrict__ ent) {
    int c = threadIdx.x;
    if (blockIdx.x >= 1531) {
        // per-pair index table
        int i = blockIdx.x - 1531;
        int res_i  = res[i];
        int sym_i  = sym[i];
        int asym_i = asym[i];
        int ent_i  = ent[i];
        for (int j = c; j < NRES; j += 256) {
            int off = res_i - res[j] + 32;
            off = min(max(off, 0), 64);
            int pos = (asym_i == asym[j]) ? off : 65;
            int sj = sym[j];
            int ed = ent_i - sj;
            int cc = sym_i - sj + 2;
            cc = min(max(cc, 0), 4);
            int chain = (ed != 0) ? cc : 5;
            g_idx[i * NRES + j] =
                (unsigned short)(((pos * 6 + chain) * 7) + (ed + 3));
        }
        return;
    }
    if (blockIdx.x >= 145) {
        // W3 table: 2 rows per block
        int row = (blockIdx.x - 145) * 2 + (c >> 7);
        int ch = c & 127;
        if (row < 2772) {
            int e = row % 7;
            int p36 = row / 7;
            int chain = p36 % 6;
            int pos = p36 / 6;
            g_w3[row * CZ + ch] = wrel[pos * CZ + ch] + wrel[(67 + chain) * CZ + ch]
                                  + (float)(e - 3) * wrel[66 * CZ + ch];
        }
        return;
    }
    if (blockIdx.x >= 96) {
        int k = blockIdx.x - 96;   // 0..48
        float v = wmsa[k * CM + c];
        if (k < 48) g_wh[k * CM + c] = __float2half_rn(v);
        else        g_w48[c] = v;
        return;
    }
    __shared__ float swm[TF * CM];
    __shared__ float swi[TF * CZ];
    __shared__ float swj[TF * CZ];
    __shared__ float st[8 * TF];

    for (int g = c; g < TF * CM; g += 256) swm[g] = wm[g];
    for (int g = c; g < TF * CZ; g += 256) { swi[g] = wzi[g]; swj[g] = wzj[g]; }
    int i0 = blockIdx.x * 8;
    for (int g = c; g < 8 * TF; g += 256) st[g] = tf[i0 * TF + g];
    __syncthreads();

    float bmv = bm[c] + bmsa[c];
    float bzi_v = (c < CZ) ? bzi[c] : 0.0f;
    float bzj_v = (c < CZ) ? bzj[c] : 0.0f;

#pragma unroll 1
    for (int r = 0; r < 8; r++) {
        const float* t = st + r * TF;
        float am = bmv;
#pragma unroll
        for (int k = 0; k < TF; k++) am += t[k] * swm[k * CM + c];
        g_comb[(i0 + r) * CM + c] = am;

        if (c < CZ) {
            float ai = bzi_v;
            float aj = bzj_v;
#pragma unroll
            for (int k = 0; k < TF; k++) {
                float tv = t[k];
                ai += tv * swi[k * CZ + c];
                aj += tv * swj[k * CZ + c];
            }
            g_tfi[(i0 + r) * CZ + c] = ai;
            g_tfj[(i0 + r) * CZ + c] = aj;
        }
    }
}

// ---------------- kernel 2: unified persistent msa + pair ----------------
__global__ void __launch_bounds__(256, 3) uni_kernel(const float* __restrict__ msa,
                                                     const float* __restrict__ b_rel,
                                                     float* __restrict__ out) {
    extern __shared__ char smem[];
    uint32_t sb = smem_u32(smem);
    int tid = threadIdx.x;
    int lane = tid & 31;
    int wid = tid >> 5;
    int bid = blockIdx.x;
    float* msa_out  = out;
    float* pair_out = out + MSA_OUT_ELEMS;

    // stage weights + w48 once
    for (int g = tid; g < 1536; g += 256) {
        int row = g >> 5;
        int c = g & 31;
        cp16(sb + OFF_W + row * W_STRIDE + c * 16, (const char*)g_wh + row * 512 + c * 16);
    }
    if (tid < 64) cp16(sb + OFF_W48 + tid * 16, (const char*)g_w48 + tid * 16);
    // prefetch first msa tile raw
    {
        int wf = bid;
        while (wf < TOT_ITEMS && (wf % 5) == 4) wf += GRID_U;
        if (wf < TOT_ITEMS) {
            int m = (wf / 5) * 4 + (wf % 5);
            const char* src = (const char*)msa + (long)m * 6272;
            for (int g = tid; g < 392; g += 256)
                cp16(sb + OFF_RAW0 + g * 16, src + g * 16);
        }
    }
    cp_commit();

    // per-thread ldmatrix addresses
    uint32_t aoff = (uint32_t)((lane & 15) * A_STRIDE + (lane >> 4) * 16);
    uint32_t ahi_base = sb + OFF_AHI + aoff;
    uint32_t boff = (uint32_t)(((lane & 7) + ((lane >> 3) & 1) * 8) * W_STRIDE +
                               (wid * 32 + (lane >> 4) * 8) * 2);
    uint32_t b_base = sb + OFF_W + boff;
    int qr = lane >> 2;
    int qc = (lane & 3) * 2;
    int msa_cnt = 0;

    const float* s_w48f = (const float*)(smem + OFF_W48);

    // ---- load B fragments ONCE (weights are tile-invariant) ----
    cp_wait_all();
    __syncthreads();
    uint32_t bfr[3][8];
#pragma unroll
    for (int ks = 0; ks < 3; ks++) {
        LDSM_X4T(&bfr[ks][0], b_base + ks * 16 * W_STRIDE);
        LDSM_X4T(&bfr[ks][4], b_base + ks * 16 * W_STRIDE + 32);  // +16 ch
    }

    for (int w = bid; w < TOT_ITEMS; w += GRID_U) {
        if ((w % 5) != 4) {
            // ================= msa tile (32 rows x 256 ch) =================
            int t = (w / 5) * 4 + (w % 5);
            uint32_t raw_cur = (msa_cnt & 1) ? OFF_RAW1 : OFF_RAW0;
            uint32_t raw_nxt = (msa_cnt & 1) ? OFF_RAW0 : OFF_RAW1;
            msa_cnt++;
            const float* rawf = (const float*)(smem + raw_cur);

            cp_wait_all();
            __syncthreads();   // raw ready; prev tile done

            // convert raw -> A fp16 (k<48)
            for (int g = tid; g < 768; g += 256) {
                int row = g / 24;
                int p = g - row * 24;
                float a0 = rawf[row * 49 + 2 * p];
                float a1 = rawf[row * 49 + 2 * p + 1];
                __half h0 = __float2half_rn(a0);
                __half h1 = __float2half_rn(a1);
                uint32_t o = row * A_STRIDE + p * 4;
                *(__half2*)(smem + OFF_AHI + o) = __halves2half2(h0, h1);
            }
            __syncthreads();   // A ready

            // prefetch next msa tile's raw (overlaps MMA)
            {
                int wn = w + GRID_U;
                while (wn < TOT_ITEMS && (wn % 5) == 4) wn += GRID_U;
                if (wn < TOT_ITEMS) {
                    int m2 = (wn / 5) * 4 + (wn % 5);
                    const char* src = (const char*)msa + (long)m2 * 6272;
                    for (int g = tid; g < 392; g += 256)
                        cp16(sb + raw_nxt + g * 16, src + g * 16);
                }
            }
            cp_commit();

            // MMA: 3 k-steps, single term; B resident
            float d[2][4][4];
#pragma unroll
            for (int mt = 0; mt < 2; mt++)
#pragma unroll
                for (int nt = 0; nt < 4; nt++)
#pragma unroll
                    for (int i = 0; i < 4; i++) d[mt][nt][i] = 0.0f;

#pragma unroll
            for (int ks = 0; ks < 3; ks++) {
                uint32_t ak = ks * 32;
                uint32_t af[2][4];
                LDSM_X4(af[0], ahi_base + ak);
                LDSM_X4(af[1], ahi_base + 16 * A_STRIDE + ak);
#pragma unroll
                for (int mt = 0; mt < 2; mt++)
#pragma unroll
                    for (int nt = 0; nt < 4; nt++)
                        MMAF16(d[mt][nt], af[mt], bfr[ks][nt * 2], bfr[ks][nt * 2 + 1]);
            }

            // ---- epilogue: 2 half passes of 16 rows, coalesced (R12) ----
            long rowbase = (long)t * 32;
            int n0 = (int)(rowbase % NRES);
#pragma unroll
            for (int p = 0; p < 2; p++) {
                {
                    char* stg = smem + OFF_STG;
                    int chb = (wid * 32 + qc) * 4;
#pragma unroll
                    for (int nt = 0; nt < 4; nt++) {
                        *(float2*)(stg + qr * STG_STRIDE + chb + nt * 32) =
                            make_float2(d[p][nt][0], d[p][nt][1]);
                        *(float2*)(stg + (qr + 8) * STG_STRIDE + chb + nt * 32) =
                            make_float2(d[p][nt][2], d[p][nt][3]);
                    }
                }
                __syncthreads();
#pragma unroll
                for (int q = 0; q < 4; q++) {
                    int g = tid + q * 256;
                    int row = g >> 6;        // 0..15
                    int c4 = g & 63;
                    float4 v = *(const float4*)(smem + OFF_STG + row * STG_STRIDE + c4 * 16);
                    float4 w48v = *(const float4*)(s_w48f + c4 * 4);
                    int grow = p * 16 + row;
                    float a48v = rawf[grow * 49 + 48];
                    float4 cb = *(const float4*)(g_comb + (n0 + grow) * CM + c4 * 4);
                    float4 o = make_float4(v.x + a48v * w48v.x + cb.x,
                                           v.y + a48v * w48v.y + cb.y,
                                           v.z + a48v * w48v.z + cb.z,
                                           v.w + a48v * w48v.w + cb.w);
                    *(float4*)(msa_out + (rowbase + grow) * (long)CM + c4 * 4) = o;
                }
                __syncthreads();
            }
        } else {
            // ================= pair tile (table-driven) =================
            int p = w / 5;
            int i = p >> 2;
            int jstart = (p & 3) * 192;
            int jl = tid >> 5;   // warp -> j lane

            float4 b4 = ((const float4*)b_rel)[lane];
            float4 ti = ((const float4*)(g_tfi + i * CZ))[lane];
            float4 base4 = make_float4(b4.x + ti.x, b4.y + ti.y, b4.z + ti.z, b4.w + ti.w);
            const float4* W34 = (const float4*)g_w3;
            const unsigned short* idxrow = g_idx + i * NRES;

#pragma unroll 4
            for (int it = 0; it < 24; it++) {
                int j = jstart + it * 8 + jl;
                unsigned int idxv = __ldg(idxrow + j);

                float4 wv = W34[idxv * 32 + lane];
                float4 tj = ((const float4*)(g_tfj + j * CZ))[lane];

                float4 o;
                o.x = base4.x + wv.x + tj.x;
                o.y = base4.y + wv.y + tj.y;
                o.z = base4.z + wv.z + tj.z;
                o.w = base4.w + wv.w + tj.w;

                ((float4*)(pair_out + ((size_t)i * NRES + j) * CZ))[lane] = o;
            }
        }
    }
}

// ---------------- launch ----------------
extern "C" void kernel_launch(void* const* d_in, const int* in_sizes, int n_in,
                              void* d_out, int out_size) {
    const float* tf     = (const float*)d_in[0];
    const float* msa    = (const float*)d_in[1];
    const int*   res    = (const int*)d_in[2];
    const int*   sym    = (const int*)d_in[3];
    const int*   asym   = (const int*)d_in[4];
    const int*   ent    = (const int*)d_in[5];
    const float* w_zi   = (const float*)d_in[6];
    const float* b_zi   = (const float*)d_in[7];
    const float* w_zj   = (const float*)d_in[8];
    const float* b_zj   = (const float*)d_in[9];
    const float* w_m    = (const float*)d_in[10];
    const float* b_m    = (const float*)d_in[11];
    const float* w_msa  = (const float*)d_in[12];
    const float* b_msa  = (const float*)d_in[13];
    const float* w_rel  = (const float*)d_in[14];
    const float* b_rel  = (const float*)d_in[15];

    cudaFuncSetAttribute(uni_kernel, cudaFuncAttributeMaxDynamicSharedMemorySize, U_SMEM);

    pre_kernel<<<96 + 49 + 1386 + 768, 256>>>(tf, w_zi, b_zi, w_zj, b_zj, w_m, b_m,
                                              b_msa, w_msa, w_rel,
                                              res, sym, asym, ent);
    uni_kernel<<<GRID_U, 256, U_SMEM>>>(msa, b_rel, (float*)d_out);
}

// round 16
// speedup vs baseline: 1.0690x; 1.0211x over previous
#include <cuda_runtime.h>
#include <cuda_fp16.h>
#include <cstdint>

// Problem constants
#define NRES 768
#define TF   21
#define MSADIM 49
#define CZ   128
#define CM   256
#define MSA_OUT_ELEMS (512u*768u*256u)   // 100663296
#define TOT_ITEMS 15360                  // 5 * 3072
#define GRID_U 444                       // 3 CTAs per SM

// ---------------- device scratch ----------------
__device__ float  g_tfi[NRES * CZ];
__device__ float  g_tfj[NRES * CZ];
__device__ float  g_comb[NRES * CM];
__device__ __half g_wh[48 * CM];         // fp16 weights k=0..47
__device__ float  g_w48[CM];             // fp32 weight row k=48
__device__ float  g_w3[2772 * CZ];       // W3[(pos*6+chain)*7+(ed+3)]
__device__ unsigned short g_idx[NRES * NRES];  // per-pair W3 row index

// ---------------- smem layout per CTA (bytes) ---- (R12 layout) ----
#define W_STRIDE 528
#define A_STRIDE 112
#define OFF_W    0
#define OFF_RAW0 25344
#define OFF_RAW1 31616
#define OFF_W48  37888
#define OFF_AHI  38912
#define OFF_STG  42496
#define STG_STRIDE 1056
#define U_SMEM   59392

// pre kernel block ranges
#define PRE_EMB   384    // blocks 0..383: 2 residues each
#define PRE_WCONV 49     // blocks 384..432
#define PRE_W3    174    // blocks 433..606: 16 W3 rows each
#define PRE_IDX   96     // blocks 607..702: 8 i-rows each
#define PRE_BLOCKS (PRE_EMB + PRE_WCONV + PRE_W3 + PRE_IDX)

// ---------------- helpers ----------------
__device__ __forceinline__ uint32_t smem_u32(const void* p) {
    uint32_t a;
    asm("{ .reg .u64 t; cvta.to.shared.u64 t, %1; cvt.u32.u64 %0, t; }" : "=r"(a) : "l"(p));
    return a;
}
__device__ __forceinline__ void cp16(uint32_t dst, const void* src) {
    asm volatile("cp.async.cg.shared.global [%0], [%1], 16;" :: "r"(dst), "l"(src) : "memory");
}
__device__ __forceinline__ void cp_commit() {
    asm volatile("cp.async.commit_group;" ::: "memory");
}
__device__ __forceinline__ void cp_wait_all() {
    asm volatile("cp.async.wait_group 0;" ::: "memory");
}

#define LDSM_X4(r, addr) \
    asm volatile("ldmatrix.sync.aligned.m8n8.x4.shared.b16 {%0,%1,%2,%3}, [%4];" \
                 : "=r"((r)[0]), "=r"((r)[1]), "=r"((r)[2]), "=r"((r)[3]) : "r"(addr))
#define LDSM_X4T(r, addr) \
    asm volatile("ldmatrix.sync.aligned.m8n8.x4.trans.shared.b16 {%0,%1,%2,%3}, [%4];" \
                 : "=r"((r)[0]), "=r"((r)[1]), "=r"((r)[2]), "=r"((r)[3]) : "r"(addr))
#define MMAF16(d, a, b0v, b1v) \
    asm volatile("mma.sync.aligned.m16n8k16.row.col.f32.f16.f16.f32 " \
                 "{%0,%1,%2,%3}, {%4,%5,%6,%7}, {%8,%9}, {%0,%1,%2,%3};" \
                 : "+f"((d)[0]), "+f"((d)[1]), "+f"((d)[2]), "+f"((d)[3]) \
                 : "r"((a)[0]), "r"((a)[1]), "r"((a)[2]), "r"((a)[3]), \
                   "r"(b0v), "r"(b1v))

// ---------------- kernel 1: precompute (compressed, 703 blocks) ----------------
__global__ void __launch_bounds__(256) pre_kernel(
        const float* __restrict__ tf,
        const float* __restrict__ wzi, const float* __restrict__ bzi,
        const float* __restrict__ wzj, const float* __restrict__ bzj,
        const float* __restrict__ wm,  const float* __restrict__ bm,
        const float* __restrict__ bmsa, const float* __restrict__ wmsa,
        const float* __restrict__ wrel,
        const int* __restrict__ res, const int* __restrict__ sym,
        const int* __restrict__ asym, const int* __restrict__ ent) {
    int c = threadIdx.x;
    int b = blockIdx.x;

    if (b < PRE_EMB) {
        // ---- embeddings: 2 residues per block, weights straight from L2 ----
        __shared__ float st[2 * TF];
        int i0 = b * 2;
        if (c < 2 * TF) st[c] = tf[i0 * TF + c];
        __syncthreads();
        float bmv = bm[c] + bmsa[c];
        float bzi_v = (c < CZ) ? bzi[c] : 0.0f;
        float bzj_v = (c < CZ) ? bzj[c] : 0.0f;
#pragma unroll
        for (int r = 0; r < 2; r++) {
            const float* t = st + r * TF;
            float am = bmv;
#pragma unroll
            for (int k = 0; k < TF; k++) am += t[k] * wm[k * CM + c];
            g_comb[(i0 + r) * CM + c] = am;
            if (c < CZ) {
                float ai = bzi_v;
                float aj = bzj_v;
#pragma unroll
                for (int k = 0; k < TF; k++) {
                    float tv = t[k];
                    ai += tv * wzi[k * CZ + c];
                    aj += tv * wzj[k * CZ + c];
                }
                g_tfi[(i0 + r) * CZ + c] = ai;
                g_tfj[(i0 + r) * CZ + c] = aj;
            }
        }
        return;
    }
    b -= PRE_EMB;
    if (b < PRE_WCONV) {
        int k = b;   // 0..48
        float v = wmsa[k * CM + c];
        if (k < 48) g_wh[k * CM + c] = __float2half_rn(v);
        else        g_w48[c] = v;
        return;
    }
    b -= PRE_WCONV;
    if (b < PRE_W3) {
        // ---- W3 table: 16 rows per block (2 rows per 256-thread pass x8) ----
        int ch = c & 127;
        int sub = c >> 7;            // 0/1
        float w66v = wrel[66 * CZ + ch];
#pragma unroll
        for (int rr = 0; rr < 8; rr++) {
            int row = b * 16 + rr * 2 + sub;
            if (row < 2772) {
                int e = row % 7;
                int p36 = row / 7;
                int chain = p36 % 6;
                int pos = p36 / 6;
                g_w3[row * CZ + ch] = wrel[pos * CZ + ch] + wrel[(67 + chain) * CZ + ch]
                                      + (float)(e - 3) * w66v;
            }
        }
        return;
    }
    b -= PRE_W3;
    {
        // ---- idx table: 8 i-rows per block ----
        int i0 = b * 8;
#pragma unroll 1
        for (int r = 0; r < 8; r++) {
            int i = i0 + r;
            int res_i  = res[i];
            int sym_i  = sym[i];
            int asym_i = asym[i];
            int ent_i  = ent[i];
            for (int j = c; j < NRES; j += 256) {
                int off = res_i - res[j] + 32;
                off = min(max(off, 0), 64);
                int pos = (asym_i == asym[j]) ? off : 65;
                int sj = sym[j];
                int ed = ent_i - sj;
                int cc = sym_i - sj + 2;
                cc = min(max(cc, 0), 4);
                int chain = (ed != 0) ? cc : 5;
                g_idx[i * NRES + j] =
                    (unsigned short)(((pos * 6 + chain) * 7) + (ed + 3));
            }
        }
    }
}

// ---------------- kernel 2: unified persistent msa + pair (R15 verbatim) ----------------
__global__ void __launch_bounds__(256, 3) uni_kernel(const float* __restrict__ msa,
                                                     const float* __restrict__ b_rel,
                                                     float* __restrict__ out) {
    extern __shared__ char smem[];
    uint32_t sb = smem_u32(smem);
    int tid = threadIdx.x;
    int lane = tid & 31;
    int wid = tid >> 5;
    int bid = blockIdx.x;
    float* msa_out  = out;
    float* pair_out = out + MSA_OUT_ELEMS;

    // stage weights + w48 once
    for (int g = tid; g < 1536; g += 256) {
        int row = g >> 5;
        int c = g & 31;
        cp16(sb + OFF_W + row * W_STRIDE + c * 16, (const char*)g_wh + row * 512 + c * 16);
    }
    if (tid < 64) cp16(sb + OFF_W48 + tid * 16, (const char*)g_w48 + tid * 16);
    // prefetch first msa tile raw
    {
        int wf = bid;
        while (wf < TOT_ITEMS && (wf % 5) == 4) wf += GRID_U;
        if (wf < TOT_ITEMS) {
            int m = (wf / 5) * 4 + (wf % 5);
            const char* src = (const char*)msa + (long)m * 6272;
            for (int g = tid; g < 392; g += 256)
                cp16(sb + OFF_RAW0 + g * 16, src + g * 16);
        }
    }
    cp_commit();

    // per-thread ldmatrix addresses
    uint32_t aoff = (uint32_t)((lane & 15) * A_STRIDE + (lane >> 4) * 16);
    uint32_t ahi_base = sb + OFF_AHI + aoff;
    uint32_t boff = (uint32_t)(((lane & 7) + ((lane >> 3) & 1) * 8) * W_STRIDE +
                               (wid * 32 + (lane >> 4) * 8) * 2);
    uint32_t b_base = sb + OFF_W + boff;
    int qr = lane >> 2;
    int qc = (lane & 3) * 2;
    int msa_cnt = 0;

    const float* s_w48f = (const float*)(smem + OFF_W48);

    // ---- load B fragments ONCE (weights are tile-invariant) ----
    cp_wait_all();
    __syncthreads();
    uint32_t bfr[3][8];
#pragma unroll
    for (int ks = 0; ks < 3; ks++) {
        LDSM_X4T(&bfr[ks][0], b_base + ks * 16 * W_STRIDE);
        LDSM_X4T(&bfr[ks][4], b_base + ks * 16 * W_STRIDE + 32);  // +16 ch
    }

    for (int w = bid; w < TOT_ITEMS; w += GRID_U) {
        if ((w % 5) != 4) {
            // ================= msa tile (32 rows x 256 ch) =================
            int t = (w / 5) * 4 + (w % 5);
            uint32_t raw_cur = (msa_cnt & 1) ? OFF_RAW1 : OFF_RAW0;
            uint32_t raw_nxt = (msa_cnt & 1) ? OFF_RAW0 : OFF_RAW1;
            msa_cnt++;
            const float* rawf = (const float*)(smem + raw_cur);

            cp_wait_all();
            __syncthreads();   // raw ready; prev tile done

            // convert raw -> A fp16 (k<48)
            for (int g = tid; g < 768; g += 256) {
                int row = g / 24;
                int p = g - row * 24;
                float a0 = rawf[row * 49 + 2 * p];
                float a1 = rawf[row * 49 + 2 * p + 1];
                __half h0 = __float2half_rn(a0);
                __half h1 = __float2half_rn(a1);
                uint32_t o = row * A_STRIDE + p * 4;
                *(__half2*)(smem + OFF_AHI + o) = __halves2half2(h0, h1);
            }
            __syncthreads();   // A ready

            // prefetch next msa tile's raw (overlaps MMA)
            {
                int wn = w + GRID_U;
                while (wn < TOT_ITEMS && (wn % 5) == 4) wn += GRID_U;
                if (wn < TOT_ITEMS) {
                    int m2 = (wn / 5) * 4 + (wn % 5);
                    const char* src = (const char*)msa + (long)m2 * 6272;
                    for (int g = tid; g < 392; g += 256)
                        cp16(sb + raw_nxt + g * 16, src + g * 16);
                }
            }
            cp_commit();

            // MMA: 3 k-steps, single term; B resident
            float d[2][4][4];
#pragma unroll
            for (int mt = 0; mt < 2; mt++)
#pragma unroll
                for (int nt = 0; nt < 4; nt++)
#pragma unroll
                    for (int i = 0; i < 4; i++) d[mt][nt][i] = 0.0f;

#pragma unroll
            for (int ks = 0; ks < 3; ks++) {
                uint32_t ak = ks * 32;
                uint32_t af[2][4];
                LDSM_X4(af[0], ahi_base + ak);
                LDSM_X4(af[1], ahi_base + 16 * A_STRIDE + ak);
#pragma unroll
                for (int mt = 0; mt < 2; mt++)
#pragma unroll
                    for (int nt = 0; nt < 4; nt++)
                        MMAF16(d[mt][nt], af[mt], bfr[ks][nt * 2], bfr[ks][nt * 2 + 1]);
            }

            // ---- epilogue: 2 half passes of 16 rows, coalesced ----
            long rowbase = (long)t * 32;
            int n0 = (int)(rowbase % NRES);
#pragma unroll
            for (int p = 0; p < 2; p++) {
                {
                    char* stg = smem + OFF_STG;
                    int chb = (wid * 32 + qc) * 4;
#pragma unroll
                    for (int nt = 0; nt < 4; nt++) {
                        *(float2*)(stg + qr * STG_STRIDE + chb + nt * 32) =
                            make_float2(d[p][nt][0], d[p][nt][1]);
                        *(float2*)(stg + (qr + 8) * STG_STRIDE + chb + nt * 32) =
                            make_float2(d[p][nt][2], d[p][nt][3]);
                    }
                }
                __syncthreads();
#pragma unroll
                for (int q = 0; q < 4; q++) {
                    int g = tid + q * 256;
                    int row = g >> 6;        // 0..15
                    int c4 = g & 63;
                    float4 v = *(const float4*)(smem + OFF_STG + row * STG_STRIDE + c4 * 16);
                    float4 w48v = *(const float4*)(s_w48f + c4 * 4);
                    int grow = p * 16 + row;
                    float a48v = rawf[grow * 49 + 48];
                    float4 cb = *(const float4*)(g_comb + (n0 + grow) * CM + c4 * 4);
                    float4 o = make_float4(v.x + a48v * w48v.x + cb.x,
                                           v.y + a48v * w48v.y + cb.y,
                                           v.z + a48v * w48v.z + cb.z,
                                           v.w + a48v * w48v.w + cb.w);
                    *(float4*)(msa_out + (rowbase + grow) * (long)CM + c4 * 4) = o;
                }
                __syncthreads();
            }
        } else {
            // ================= pair tile (table-driven) =================
            int p = w / 5;
            int i = p >> 2;
            int jstart = (p & 3) * 192;
            int jl = tid >> 5;   // warp -> j lane

            float4 b4 = ((const float4*)b_rel)[lane];
            float4 ti = ((const float4*)(g_tfi + i * CZ))[lane];
            float4 base4 = make_float4(b4.x + ti.x, b4.y + ti.y, b4.z + ti.z, b4.w + ti.w);
            const float4* W34 = (const float4*)g_w3;
            const unsigned short* idxrow = g_idx + i * NRES;

#pragma unroll 4
            for (int it = 0; it < 24; it++) {
                int j = jstart + it * 8 + jl;
                unsigned int idxv = __ldg(idxrow + j);

                float4 wv = W34[idxv * 32 + lane];
                float4 tj = ((const float4*)(g_tfj + j * CZ))[lane];

                float4 o;
                o.x = base4.x + wv.x + tj.x;
                o.y = base4.y + wv.y + tj.y;
                o.z = base4.z + wv.z + tj.z;
                o.w = base4.w + wv.w + tj.w;

                ((float4*)(pair_out + ((size_t)i * NRES + j) * CZ))[lane] = o;
            }
        }
    }
}

// ---------------- launch ----------------
extern "C" void kernel_launch(void* const* d_in, const int* in_sizes, int n_in,
                              void* d_out, int out_size) {
    const float* tf     = (const float*)d_in[0];
    const float* msa    = (const float*)d_in[1];
    const int*   res    = (const int*)d_in[2];
    const int*   sym    = (const int*)d_in[3];
    const int*   asym   = (const int*)d_in[4];
    const int*   ent    = (const int*)d_in[5];
    const float* w_zi   = (const float*)d_in[6];
    const float* b_zi   = (const float*)d_in[7];
    const float* w_zj   = (const float*)d_in[8];
    const float* b_zj   = (const float*)d_in[9];
    const float* w_m    = (const float*)d_in[10];
    const float* b_m    = (const float*)d_in[11];
    const float* w_msa  = (const float*)d_in[12];
    const float* b_msa  = (const float*)d_in[13];
    const float* w_rel  = (const float*)d_in[14];
    const float* b_rel  = (const float*)d_in[15];

    cudaFuncSetAttribute(uni_kernel, cudaFuncAttributeMaxDynamicSharedMemorySize, U_SMEM);

    pre_kernel<<<PRE_BLOCKS, 256>>>(tf, w_zi, b_zi, w_zj, b_zj, w_m, b_m,
                                    b_msa, w_msa, w_rel, res, sym, asym, ent);
    uni_kernel<<<GRID_U, 256, U_SMEM>>>(msa, b_rel, (float*)d_out);
}

// round 17
// speedup vs baseline: 1.1367x; 1.0633x over previous
#include <cuda_runtime.h>
#include <cuda_fp16.h>
#include <cstdint>

// Problem constants
#define NRES 768
#define TF   21
#define MSADIM 49
#define CZ   128
#define CM   256
#define MSA_OUT_ELEMS (512u*768u*256u)   // 100663296
#define TOT_ITEMS 15360                  // 5 * 3072
#define GRID_U 592                       // 4 CTAs per SM

// ---------------- device scratch ----------------
__device__ float  g_tfi[NRES * CZ];
__device__ float  g_tfj[NRES * CZ];
__device__ float  g_comb[NRES * CM];
__device__ __half g_wh[48 * CM];         // fp16 weights k=0..47
__device__ float  g_w48[CM];             // fp32 weight row k=48
__device__ float  g_w3[2772 * CZ];       // W3[(pos*6+chain)*7+(ed+3)]
__device__ unsigned short g_idx[NRES * NRES];  // per-pair W3 row index

// ---------------- smem layout per CTA (bytes) ---- (R14 layout) ----
// W    [48][264h] stride 528   @ 0       (25344)  -- DEAD after bfr load;
//                                                    reused as stg rows 0..23
// raw0 32x49 f32               @ 25344   (6272)
// raw1                         @ 31616   (6272)
// w48  fp32[256]               @ 37888   (1024)
// A_hi [32][56h]  stride 112   @ 38912   (3584)
// stgB rows 24..31 x 1056B     @ 42496   (8448)  -> 50944 (4 CTAs: 203.8KB)
#define W_STRIDE 528
#define A_STRIDE 112
#define OFF_W    0
#define OFF_RAW0 25344
#define OFF_RAW1 31616
#define OFF_W48  37888
#define OFF_AHI  38912
#define OFF_STGB 42496
#define STG_STRIDE 1056
#define U_SMEM   50944

// pre kernel block ranges
#define PRE_EMB   384
#define PRE_WCONV 49
#define PRE_W3    174
#define PRE_IDX   96
#define PRE_BLOCKS (PRE_EMB + PRE_WCONV + PRE_W3 + PRE_IDX)

// ---------------- helpers ----------------
__device__ __forceinline__ uint32_t smem_u32(const void* p) {
    uint32_t a;
    asm("{ .reg .u64 t; cvta.to.shared.u64 t, %1; cvt.u32.u64 %0, t; }" : "=r"(a) : "l"(p));
    return a;
}
__device__ __forceinline__ void cp16(uint32_t dst, const void* src) {
    asm volatile("cp.async.cg.shared.global [%0], [%1], 16;" :: "r"(dst), "l"(src) : "memory");
}
__device__ __forceinline__ void cp_commit() {
    asm volatile("cp.async.commit_group;" ::: "memory");
}
__device__ __forceinline__ void cp_wait_all() {
    asm volatile("cp.async.wait_group 0;" ::: "memory");
}

#define LDSM_X4(r, addr) \
    asm volatile("ldmatrix.sync.aligned.m8n8.x4.shared.b16 {%0,%1,%2,%3}, [%4];" \
                 : "=r"((r)[0]), "=r"((r)[1]), "=r"((r)[2]), "=r"((r)[3]) : "r"(addr))
#define LDSM_X4T(r, addr) \
    asm volatile("ldmatrix.sync.aligned.m8n8.x4.trans.shared.b16 {%0,%1,%2,%3}, [%4];" \
                 : "=r"((r)[0]), "=r"((r)[1]), "=r"((r)[2]), "=r"((r)[3]) : "r"(addr))
#define MMAF16(d, a, b0v, b1v) \
    asm volatile("mma.sync.aligned.m16n8k16.row.col.f32.f16.f16.f32 " \
                 "{%0,%1,%2,%3}, {%4,%5,%6,%7}, {%8,%9}, {%0,%1,%2,%3};" \
                 : "+f"((d)[0]), "+f"((d)[1]), "+f"((d)[2]), "+f"((d)[3]) \
                 : "r"((a)[0]), "r"((a)[1]), "r"((a)[2]), "r"((a)[3]), \
                   "r"(b0v), "r"(b1v))

// ---------------- kernel 1: precompute (compressed, 703 blocks) ----------------
__global__ void __launch_bounds__(256) pre_kernel(
        const float* __restrict__ tf,
        const float* __restrict__ wzi, const float* __restrict__ bzi,
        const float* __restrict__ wzj, const float* __restrict__ bzj,
        const float* __restrict__ wm,  const float* __restrict__ bm,
        const float* __restrict__ bmsa, const float* __restrict__ wmsa,
        const float* __restrict__ wrel,
        const int* __restrict__ res, const int* __restrict__ sym,
        const int* __restrict__ asym, const int* __restrict__ ent) {
    int c = threadIdx.x;
    int b = blockIdx.x;

    if (b < PRE_EMB) {
        __shared__ float st[2 * TF];
        int i0 = b * 2;
        if (c < 2 * TF) st[c] = tf[i0 * TF + c];
        __syncthreads();
        float bmv = bm[c] + bmsa[c];
        float bzi_v = (c < CZ) ? bzi[c] : 0.0f;
        float bzj_v = (c < CZ) ? bzj[c] : 0.0f;
#pragma unroll
        for (int r = 0; r < 2; r++) {
            const float* t = st + r * TF;
            float am = bmv;
#pragma unroll
            for (int k = 0; k < TF; k++) am += t[k] * wm[k * CM + c];
            g_comb[(i0 + r) * CM + c] = am;
            if (c < CZ) {
                float ai = bzi_v;
                float aj = bzj_v;
#pragma unroll
                for (int k = 0; k < TF; k++) {
                    float tv = t[k];
                    ai += tv * wzi[k * CZ + c];
                    aj += tv * wzj[k * CZ + c];
                }
                g_tfi[(i0 + r) * CZ + c] = ai;
                g_tfj[(i0 + r) * CZ + c] = aj;
            }
        }
        return;
    }
    b -= PRE_EMB;
    if (b < PRE_WCONV) {
        int k = b;
        float v = wmsa[k * CM + c];
        if (k < 48) g_wh[k * CM + c] = __float2half_rn(v);
        else        g_w48[c] = v;
        return;
    }
    b -= PRE_WCONV;
    if (b < PRE_W3) {
        int ch = c & 127;
        int sub = c >> 7;
        float w66v = wrel[66 * CZ + ch];
#pragma unroll
        for (int rr = 0; rr < 8; rr++) {
            int row = b * 16 + rr * 2 + sub;
            if (row < 2772) {
                int e = row % 7;
                int p36 = row / 7;
                int chain = p36 % 6;
                int pos = p36 / 6;
                g_w3[row * CZ + ch] = wrel[pos * CZ + ch] + wrel[(67 + chain) * CZ + ch]
                                      + (float)(e - 3) * w66v;
            }
        }
        return;
    }
    b -= PRE_W3;
    {
        int i0 = b * 8;
#pragma unroll 1
        for (int r = 0; r < 8; r++) {
            int i = i0 + r;
            int res_i  = res[i];
            int sym_i  = sym[i];
            int asym_i = asym[i];
            int ent_i  = ent[i];
            for (int j = c; j < NRES; j += 256) {
                int off = res_i - res[j] + 32;
                off = min(max(off, 0), 64);
                int pos = (asym_i == asym[j]) ? off : 65;
                int sj = sym[j];
                int ed = ent_i - sj;
                int cc = sym_i - sj + 2;
                cc = min(max(cc, 0), 4);
                int chain = (ed != 0) ? cc : 5;
                g_idx[i * NRES + j] =
                    (unsigned short)(((pos * 6 + chain) * 7) + (ed + 3));
            }
        }
    }
}

// ---------------- kernel 2: unified persistent msa + pair (4 CTAs/SM) ----------------
__global__ void __launch_bounds__(256, 4) uni_kernel(const float* __restrict__ msa,
                                                     const float* __restrict__ b_rel,
                                                     float* __restrict__ out) {
    extern __shared__ char smem[];
    uint32_t sb = smem_u32(smem);
    int tid = threadIdx.x;
    int lane = tid & 31;
    int wid = tid >> 5;
    int bid = blockIdx.x;
    float* msa_out  = out;
    float* pair_out = out + MSA_OUT_ELEMS;

    // stage weights + w48 once
    for (int g = tid; g < 1536; g += 256) {
        int row = g >> 5;
        int c = g & 31;
        cp16(sb + OFF_W + row * W_STRIDE + c * 16, (const char*)g_wh + row * 512 + c * 16);
    }
    if (tid < 64) cp16(sb + OFF_W48 + tid * 16, (const char*)g_w48 + tid * 16);
    // prefetch first msa tile raw
    {
        int wf = bid;
        while (wf < TOT_ITEMS && (wf % 5) == 4) wf += GRID_U;
        if (wf < TOT_ITEMS) {
            int m = (wf / 5) * 4 + (wf % 5);
            const char* src = (const char*)msa + (long)m * 6272;
            for (int g = tid; g < 392; g += 256)
                cp16(sb + OFF_RAW0 + g * 16, src + g * 16);
        }
    }
    cp_commit();

    // per-thread ldmatrix addresses
    uint32_t aoff = (uint32_t)((lane & 15) * A_STRIDE + (lane >> 4) * 16);
    uint32_t ahi_base = sb + OFF_AHI + aoff;
    uint32_t boff = (uint32_t)(((lane & 7) + ((lane >> 3) & 1) * 8) * W_STRIDE +
                               (wid * 32 + (lane >> 4) * 8) * 2);
    uint32_t b_base = sb + OFF_W + boff;
    int qr = lane >> 2;
    int qc = (lane & 3) * 2;
    int msa_cnt = 0;

    const float* s_w48f = (const float*)(smem + OFF_W48);

    // ---- load B fragments ONCE; W smem region becomes dead after this ----
    cp_wait_all();
    __syncthreads();
    uint32_t bfr[3][8];
#pragma unroll
    for (int ks = 0; ks < 3; ks++) {
        LDSM_X4T(&bfr[ks][0], b_base + ks * 16 * W_STRIDE);
        LDSM_X4T(&bfr[ks][4], b_base + ks * 16 * W_STRIDE + 32);  // +16 ch
    }

    for (int w = bid; w < TOT_ITEMS; w += GRID_U) {
        if ((w % 5) != 4) {
            // ================= msa tile (32 rows x 256 ch) =================
            int t = (w / 5) * 4 + (w % 5);
            uint32_t raw_cur = (msa_cnt & 1) ? OFF_RAW1 : OFF_RAW0;
            uint32_t raw_nxt = (msa_cnt & 1) ? OFF_RAW0 : OFF_RAW1;
            msa_cnt++;
            const float* rawf = (const float*)(smem + raw_cur);

            cp_wait_all();
            __syncthreads();   // raw ready; prev tile done

            // convert raw -> A fp16 (k<48)
            for (int g = tid; g < 768; g += 256) {
                int row = g / 24;
                int p = g - row * 24;
                float a0 = rawf[row * 49 + 2 * p];
                float a1 = rawf[row * 49 + 2 * p + 1];
                __half h0 = __float2half_rn(a0);
                __half h1 = __float2half_rn(a1);
                uint32_t o = row * A_STRIDE + p * 4;
                *(__half2*)(smem + OFF_AHI + o) = __halves2half2(h0, h1);
            }
            __syncthreads();   // A ready

            // prefetch next msa tile's raw (overlaps MMA)
            {
                int wn = w + GRID_U;
                while (wn < TOT_ITEMS && (wn % 5) == 4) wn += GRID_U;
                if (wn < TOT_ITEMS) {
                    int m2 = (wn / 5) * 4 + (wn % 5);
                    const char* src = (const char*)msa + (long)m2 * 6272;
                    for (int g = tid; g < 392; g += 256)
                        cp16(sb + raw_nxt + g * 16, src + g * 16);
                }
            }
            cp_commit();

            // MMA: 3 k-steps, single term; B resident
            float d[2][4][4];
#pragma unroll
            for (int mt = 0; mt < 2; mt++)
#pragma unroll
                for (int nt = 0; nt < 4; nt++)
#pragma unroll
                    for (int i = 0; i < 4; i++) d[mt][nt][i] = 0.0f;

#pragma unroll
            for (int ks = 0; ks < 3; ks++) {
                uint32_t ak = ks * 32;
                uint32_t af[2][4];
                LDSM_X4(af[0], ahi_base + ak);
                LDSM_X4(af[1], ahi_base + 16 * A_STRIDE + ak);
#pragma unroll
                for (int mt = 0; mt < 2; mt++)
#pragma unroll
                    for (int nt = 0; nt < 4; nt++)
                        MMAF16(d[mt][nt], af[mt], bfr[ks][nt * 2], bfr[ks][nt * 2 + 1]);
            }

            // ---- epilogue: single-pass 32-row staging (rows 0..23 in dead W
            //      region, rows 24..31 in stgB), 2 syncs ----
            long rowbase = (long)t * 32;
            int n0 = (int)(rowbase % NRES);
            {
                char* stgA = smem;               // rows 0..23
                char* stgB = smem + OFF_STGB;    // rows 24..31
                int chb = (wid * 32 + qc) * 4;
#pragma unroll
                for (int nt = 0; nt < 4; nt++) {
                    *(float2*)(stgA + qr * STG_STRIDE + chb + nt * 32) =
                        make_float2(d[0][nt][0], d[0][nt][1]);
                    *(float2*)(stgA + (qr + 8) * STG_STRIDE + chb + nt * 32) =
                        make_float2(d[0][nt][2], d[0][nt][3]);
                    *(float2*)(stgA + (16 + qr) * STG_STRIDE + chb + nt * 32) =
                        make_float2(d[1][nt][0], d[1][nt][1]);
                    *(float2*)(stgB + qr * STG_STRIDE + chb + nt * 32) =
                        make_float2(d[1][nt][2], d[1][nt][3]);
                }
            }
            __syncthreads();
#pragma unroll
            for (int q = 0; q < 8; q++) {
                int g = tid + q * 256;
                int row = g >> 6;        // 0..31; q<6 -> row<24 (region A)
                int c4 = g & 63;
                float4 v = (q < 6)
                    ? *(const float4*)(smem + row * STG_STRIDE + c4 * 16)
                    : *(const float4*)(smem + OFF_STGB + (row - 24) * STG_STRIDE + c4 * 16);
                float4 w48v = *(const float4*)(s_w48f + c4 * 4);
                float a48v = rawf[row * 49 + 48];
                float4 cb = *(const float4*)(g_comb + (n0 + row) * CM + c4 * 4);
                float4 o = make_float4(v.x + a48v * w48v.x + cb.x,
                                       v.y + a48v * w48v.y + cb.y,
                                       v.z + a48v * w48v.z + cb.z,
                                       v.w + a48v * w48v.w + cb.w);
                *(float4*)(msa_out + (rowbase + row) * (long)CM + c4 * 4) = o;
            }
            __syncthreads();
        } else {
            // ================= pair tile (table-driven) =================
            int p = w / 5;
            int i = p >> 2;
            int jstart = (p & 3) * 192;
            int jl = tid >> 5;

            float4 b4 = ((const float4*)b_rel)[lane];
            float4 ti = ((const float4*)(g_tfi + i * CZ))[lane];
            float4 base4 = make_float4(b4.x + ti.x, b4.y + ti.y, b4.z + ti.z, b4.w + ti.w);
            const float4* W34 = (const float4*)g_w3;
            const unsigned short* idxrow = g_idx + i * NRES;

#pragma unroll 4
            for (int it = 0; it < 24; it++) {
                int j = jstart + it * 8 + jl;
                unsigned int idxv = __ldg(idxrow + j);

                float4 wv = W34[idxv * 32 + lane];
                float4 tj = ((const float4*)(g_tfj + j * CZ))[lane];

                float4 o;
                o.x = base4.x + wv.x + tj.x;
                o.y = base4.y + wv.y + tj.y;
                o.z = base4.z + wv.z + tj.z;
                o.w = base4.w + wv.w + tj.w;

                ((float4*)(pair_out + ((size_t)i * NRES + j) * CZ))[lane] = o;
            }
        }
    }
}

// ---------------- launch ----------------
extern "C" void kernel_launch(void* const* d_in, const int* in_sizes, int n_in,
                              void* d_out, int out_size) {
    const float* tf     = (const float*)d_in[0];
    const float* msa    = (const float*)d_in[1];
    const int*   res    = (const int*)d_in[2];
    const int*   sym    = (const int*)d_in[3];
    const int*   asym   = (const int*)d_in[4];
    const int*   ent    = (const int*)d_in[5];
    const float* w_zi   = (const float*)d_in[6];
    const float* b_zi   = (const float*)d_in[7];
    const float* w_zj   = (const float*)d_in[8];
    const float* b_zj   = (const float*)d_in[9];
    const float* w_m    = (const float*)d_in[10];
    const float* b_m    = (const float*)d_in[11];
    const float* w_msa  = (const float*)d_in[12];
    const float* b_msa  = (const float*)d_in[13];
    const float* w_rel  = (const float*)d_in[14];
    const float* b_rel  = (const float*)d_in[15];

    cudaFuncSetAttribute(uni_kernel, cudaFuncAttributeMaxDynamicSharedMemorySize, U_SMEM);

    pre_kernel<<<PRE_BLOCKS, 256>>>(tf, w_zi, b_zi, w_zj, b_zj, w_m, b_m,
                                    b_msa, w_msa, w_rel, res, sym, asym, ent);
    uni_kernel<<<GRID_U, 256, U_SMEM>>>(msa, b_rel, (float*)d_out);
}